// round 7
// baseline (speedup 1.0000x reference)
#include <cuda_runtime.h>
#include <cuda_fp16.h>

#define N_NODES 50000
#define N_EDGES 800000
#define D_FEAT  64
#define ROWS_PER_BLOCK 8

// Precomputed CSR row pointers.
__device__ int g_row_ptr[N_NODES + 1];
// fp16 copy of embeds: one 128B line per row. 6.4MB, L2-resident.
__device__ __half2 g_emb_h[N_NODES * D_FEAT / 2];

// Kernel A: one thread per boundary, independent binary searches.
__global__ __launch_bounds__(256)
void build_row_ptr_kernel(const int* __restrict__ row_idx) {
    const int t = blockIdx.x * blockDim.x + threadIdx.x;
    if (t > N_NODES) return;
    int lo = 0, hi = N_EDGES;
    while (lo < hi) {
        const int mid = (lo + hi) >> 1;
        if (__ldg(row_idx + mid) < t) lo = mid + 1; else hi = mid;
    }
    g_row_ptr[t] = lo;
}

// Kernel C: fp32 -> fp16 embed conversion. Each thread: 8 floats -> 8 halves.
__global__ __launch_bounds__(256)
void convert_embeds_kernel(const float* __restrict__ embeds) {
    const int t = blockIdx.x * blockDim.x + threadIdx.x;
    if (t >= N_NODES * D_FEAT / 8) return;
    const float4* e4 = reinterpret_cast<const float4*>(embeds);
    const float4 a = __ldg(e4 + 2 * t);
    const float4 b = __ldg(e4 + 2 * t + 1);
    __half2* dst = g_emb_h + 4 * t;
    dst[0] = __float22half2_rn(make_float2(a.x, a.y));
    dst[1] = __float22half2_rn(make_float2(a.z, a.w));
    dst[2] = __float22half2_rn(make_float2(b.x, b.y));
    dst[3] = __float22half2_rn(make_float2(b.z, b.w));
}

// Kernel B: warp-per-row SpMM on fp16 embeds, fp32 math.
// Quarter-warp (8 lanes x uint4 = 128B) covers one embed row; one LDG.128
// warp instruction gathers 4 edges (groups g=0..3 handle edges e+g).
// Gather traffic halves vs fp32 (102.4MB); LDG count = 0.75 instr/edge.
__global__ __launch_bounds__(ROWS_PER_BLOCK * 32)
void gcn_spmm_kernel(const int* __restrict__ col_idx,
                     const float* __restrict__ vals,
                     float* __restrict__ out) {
    const int tid  = threadIdx.x;
    const int wid  = tid >> 5;
    const int lane = tid & 31;
    const int g    = lane >> 3;          // edge group 0..3
    const int q    = lane & 7;           // dim slice: halves [8q .. 8q+7]
    const int row  = blockIdx.x * ROWS_PER_BLOCK + wid;

    const int start = __ldg(&g_row_ptr[row]);
    const int end   = __ldg(&g_row_ptr[row + 1]);
    const int endm1 = end - 1;           // only touched when loop runs

    const uint4* __restrict__ emb16 = reinterpret_cast<const uint4*>(g_emb_h);

    float a0 = 0.f, a1 = 0.f, a2 = 0.f, a3 = 0.f;
    float a4 = 0.f, a5 = 0.f, a6 = 0.f, a7 = 0.f;

    for (int e = start; e < end; e += 4) {
        const int eidx = e + g;
        const int idx  = min(eidx, endm1);              // always valid
        const int   c  = __ldg(col_idx + idx);          // 4-addr broadcast
        const float vl = __ldg(vals + idx);
        const float v  = (eidx < end) ? vl : 0.0f;      // phantom -> 0
        const uint4 x  = __ldg(emb16 + (size_t)c * 8 + q);  // 16B of the row

        const float2 f0 = __half22float2(*reinterpret_cast<const __half2*>(&x.x));
        const float2 f1 = __half22float2(*reinterpret_cast<const __half2*>(&x.y));
        const float2 f2 = __half22float2(*reinterpret_cast<const __half2*>(&x.z));
        const float2 f3 = __half22float2(*reinterpret_cast<const __half2*>(&x.w));
        a0 = fmaf(v, f0.x, a0);  a1 = fmaf(v, f0.y, a1);
        a2 = fmaf(v, f1.x, a2);  a3 = fmaf(v, f1.y, a3);
        a4 = fmaf(v, f2.x, a4);  a5 = fmaf(v, f2.y, a5);
        a6 = fmaf(v, f3.x, a6);  a7 = fmaf(v, f3.y, a7);
    }

    // Fold the 4 edge groups: g2,g3 -> g0,g1 then g1 -> g0.
    #pragma unroll
    for (int ofs = 16; ofs >= 8; ofs >>= 1) {
        a0 += __shfl_down_sync(0xffffffffu, a0, ofs);
        a1 += __shfl_down_sync(0xffffffffu, a1, ofs);
        a2 += __shfl_down_sync(0xffffffffu, a2, ofs);
        a3 += __shfl_down_sync(0xffffffffu, a3, ofs);
        a4 += __shfl_down_sync(0xffffffffu, a4, ofs);
        a5 += __shfl_down_sync(0xffffffffu, a5, ofs);
        a6 += __shfl_down_sync(0xffffffffu, a6, ofs);
        a7 += __shfl_down_sync(0xffffffffu, a7, ofs);
    }

    // Lanes 0-7 store the 256B fp32 row (two coalesced STG.128 waves).
    if (g == 0) {
        float4* o4 = reinterpret_cast<float4*>(out + (size_t)row * D_FEAT + q * 8);
        o4[0] = make_float4(a0, a1, a2, a3);
        o4[1] = make_float4(a4, a5, a6, a7);
    }
}

extern "C" void kernel_launch(void* const* d_in, const int* in_sizes, int n_in,
                              void* d_out, int out_size) {
    const int*   row_idx = (const int*)  d_in[0];
    const int*   col_idx = (const int*)  d_in[1];
    const float* vals    = (const float*)d_in[2];
    const float* embeds  = (const float*)d_in[3];
    float*       out     = (float*)d_out;

    build_row_ptr_kernel<<<(N_NODES + 1 + 255) / 256, 256>>>(row_idx);
    convert_embeds_kernel<<<(N_NODES * D_FEAT / 8 + 255) / 256, 256>>>(embeds);

    const int blocks = N_NODES / ROWS_PER_BLOCK;   // 6250
    gcn_spmm_kernel<<<blocks, ROWS_PER_BLOCK * 32>>>(col_idx, vals, out);
}

// round 8
// speedup vs baseline: 1.1075x; 1.1075x over previous
#include <cuda_runtime.h>
#include <cuda_fp16.h>

#define N_NODES 50000
#define N_EDGES 800000
#define D_FEAT  64
#define ROWS_PER_BLOCK 8
#define CONV_THREADS (N_NODES * D_FEAT / 8)   // 400000

// Precomputed CSR row pointers.
__device__ int g_row_ptr[N_NODES + 1];
// fp16 copy of embeds: one 128B line per row. 6.4MB, L2-resident.
__device__ __half2 g_emb_h[N_NODES * D_FEAT / 2];

// Fused prep kernel (one launch, all-parallel, no dependent chains):
//  - threads 0..N_EDGES: O(E) scatter build of row_ptr from sorted row_idx
//    (thread t writes ptr[r]=t for r in (row[t-1], row[t]]; expected loop
//    length N/E = 0.06)
//  - threads < CONV_THREADS additionally convert 8 floats -> 8 halves.
__global__ __launch_bounds__(256)
void prep_kernel(const int* __restrict__ row_idx,
                 const float* __restrict__ embeds) {
    const int t = blockIdx.x * blockDim.x + threadIdx.x;

    if (t <= N_EDGES) {
        if (t == 0) {
            const int r1 = __ldg(row_idx + 0);
            for (int r = 0; r <= r1; r++) g_row_ptr[r] = 0;
        } else {
            const int r0 = __ldg(row_idx + t - 1);
            const int r1 = (t < N_EDGES) ? __ldg(row_idx + t) : N_NODES;
            for (int r = r0 + 1; r <= r1; r++) g_row_ptr[r] = t;
        }
    }

    if (t < CONV_THREADS) {
        const float4* e4 = reinterpret_cast<const float4*>(embeds);
        const float4 a = __ldg(e4 + 2 * t);
        const float4 b = __ldg(e4 + 2 * t + 1);
        __half2* dst = g_emb_h + 4 * t;
        dst[0] = __float22half2_rn(make_float2(a.x, a.y));
        dst[1] = __float22half2_rn(make_float2(a.z, a.w));
        dst[2] = __float22half2_rn(make_float2(b.x, b.y));
        dst[3] = __float22half2_rn(make_float2(b.z, b.w));
    }
}

// Kernel B: warp-per-row SpMM on fp16 embeds, fp32 math.
// Quarter-warp (8 lanes x uint4 = 128B) covers one embed row; one LDG.128
// warp instruction gathers 4 edges (groups g=0..3 handle edges e+g).
__global__ __launch_bounds__(ROWS_PER_BLOCK * 32)
void gcn_spmm_kernel(const int* __restrict__ col_idx,
                     const float* __restrict__ vals,
                     float* __restrict__ out) {
    const int tid  = threadIdx.x;
    const int wid  = tid >> 5;
    const int lane = tid & 31;
    const int g    = lane >> 3;          // edge group 0..3
    const int q    = lane & 7;           // dim slice: halves [8q .. 8q+7]
    const int row  = blockIdx.x * ROWS_PER_BLOCK + wid;

    const int start = __ldg(&g_row_ptr[row]);
    const int end   = __ldg(&g_row_ptr[row + 1]);
    const int endm1 = end - 1;           // only touched when loop runs

    const uint4* __restrict__ emb16 = reinterpret_cast<const uint4*>(g_emb_h);

    float a0 = 0.f, a1 = 0.f, a2 = 0.f, a3 = 0.f;
    float a4 = 0.f, a5 = 0.f, a6 = 0.f, a7 = 0.f;

    for (int e = start; e < end; e += 4) {
        const int eidx = e + g;
        const int idx  = min(eidx, endm1);              // always valid
        const int   c  = __ldg(col_idx + idx);          // 4-addr broadcast
        const float vl = __ldg(vals + idx);
        const float v  = (eidx < end) ? vl : 0.0f;      // phantom -> 0
        const uint4 x  = __ldg(emb16 + (size_t)c * 8 + q);  // 16B of the row

        const float2 f0 = __half22float2(*reinterpret_cast<const __half2*>(&x.x));
        const float2 f1 = __half22float2(*reinterpret_cast<const __half2*>(&x.y));
        const float2 f2 = __half22float2(*reinterpret_cast<const __half2*>(&x.z));
        const float2 f3 = __half22float2(*reinterpret_cast<const __half2*>(&x.w));
        a0 = fmaf(v, f0.x, a0);  a1 = fmaf(v, f0.y, a1);
        a2 = fmaf(v, f1.x, a2);  a3 = fmaf(v, f1.y, a3);
        a4 = fmaf(v, f2.x, a4);  a5 = fmaf(v, f2.y, a5);
        a6 = fmaf(v, f3.x, a6);  a7 = fmaf(v, f3.y, a7);
    }

    // Fold the 4 edge groups: g2,g3 -> g0,g1 then g1 -> g0.
    #pragma unroll
    for (int ofs = 16; ofs >= 8; ofs >>= 1) {
        a0 += __shfl_down_sync(0xffffffffu, a0, ofs);
        a1 += __shfl_down_sync(0xffffffffu, a1, ofs);
        a2 += __shfl_down_sync(0xffffffffu, a2, ofs);
        a3 += __shfl_down_sync(0xffffffffu, a3, ofs);
        a4 += __shfl_down_sync(0xffffffffu, a4, ofs);
        a5 += __shfl_down_sync(0xffffffffu, a5, ofs);
        a6 += __shfl_down_sync(0xffffffffu, a6, ofs);
        a7 += __shfl_down_sync(0xffffffffu, a7, ofs);
    }

    // Lanes 0-7 store the 256B fp32 row (two coalesced STG.128 waves).
    if (g == 0) {
        float4* o4 = reinterpret_cast<float4*>(out + (size_t)row * D_FEAT + q * 8);
        o4[0] = make_float4(a0, a1, a2, a3);
        o4[1] = make_float4(a4, a5, a6, a7);
    }
}

extern "C" void kernel_launch(void* const* d_in, const int* in_sizes, int n_in,
                              void* d_out, int out_size) {
    const int*   row_idx = (const int*)  d_in[0];
    const int*   col_idx = (const int*)  d_in[1];
    const float* vals    = (const float*)d_in[2];
    const float* embeds  = (const float*)d_in[3];
    float*       out     = (float*)d_out;

    prep_kernel<<<(N_EDGES + 1 + 255) / 256, 256>>>(row_idx, embeds);

    const int blocks = N_NODES / ROWS_PER_BLOCK;   // 6250
    gcn_spmm_kernel<<<blocks, ROWS_PER_BLOCK * 32>>>(col_idx, vals, out);
}

// round 9
// speedup vs baseline: 1.2167x; 1.0986x over previous
#include <cuda_runtime.h>
#include <cuda_fp16.h>

#define N_NODES 50000
#define N_EDGES 800000
#define D_FEAT  64
#define ROWS_PER_BLOCK 8
#define CONV_THREADS (N_NODES * D_FEAT / 8)   // 400000

// Precomputed CSR row pointers.
__device__ int g_row_ptr[N_NODES + 1];
// fp16 copy of embeds: one 128B line per row. 6.4MB, L2-resident.
__device__ __half2 g_emb_h[N_NODES * D_FEAT / 2];

// Fused prep: O(E) scatter row_ptr build + fp32->fp16 embed convert.
__global__ __launch_bounds__(256)
void prep_kernel(const int* __restrict__ row_idx,
                 const float* __restrict__ embeds) {
    const int t = blockIdx.x * blockDim.x + threadIdx.x;

    if (t <= N_EDGES) {
        if (t == 0) {
            const int r1 = __ldg(row_idx + 0);
            for (int r = 0; r <= r1; r++) g_row_ptr[r] = 0;
        } else {
            const int r0 = __ldg(row_idx + t - 1);
            const int r1 = (t < N_EDGES) ? __ldg(row_idx + t) : N_NODES;
            for (int r = r0 + 1; r <= r1; r++) g_row_ptr[r] = t;
        }
    }

    if (t < CONV_THREADS) {
        const float4* e4 = reinterpret_cast<const float4*>(embeds);
        const float4 a = __ldg(e4 + 2 * t);
        const float4 b = __ldg(e4 + 2 * t + 1);
        __half2* dst = g_emb_h + 4 * t;
        dst[0] = __float22half2_rn(make_float2(a.x, a.y));
        dst[1] = __float22half2_rn(make_float2(a.z, a.w));
        dst[2] = __float22half2_rn(make_float2(b.x, b.y));
        dst[3] = __float22half2_rn(make_float2(b.z, b.w));
    }
}

// Packed f32x2 helpers (ptxas never auto-fuses these; PTX-only path).
__device__ __forceinline__ unsigned long long pk2(float lo, float hi) {
    unsigned long long r;
    asm("mov.b64 %0, {%1, %2};" : "=l"(r) : "f"(lo), "f"(hi));
    return r;
}
__device__ __forceinline__ void ffma2(unsigned long long& acc,
                                      unsigned long long x,
                                      unsigned long long v) {
    asm("fma.rn.f32x2 %0, %1, %2, %3;" : "=l"(acc) : "l"(x), "l"(v), "l"(acc));
}
__device__ __forceinline__ float2 unpk2(unsigned long long p) {
    float2 f;
    asm("mov.b64 {%0, %1}, %2;" : "=f"(f.x), "=f"(f.y) : "l"(p));
    return f;
}

// Kernel B: warp-per-row SpMM on fp16 embeds, fp32 math.
// Quarter-warp (8 lanes x uint4 = 128B) covers one embed row; one LDG.128
// gathers 4 edges. Main loop: 8 edges/iter, 2 independent gathers (MLP=2),
// no clamps/selects; packed FFMA2 math. Tail (<8 edges): clamped, selected.
__global__ __launch_bounds__(ROWS_PER_BLOCK * 32)
void gcn_spmm_kernel(const int* __restrict__ col_idx,
                     const float* __restrict__ vals,
                     float* __restrict__ out) {
    const int tid  = threadIdx.x;
    const int wid  = tid >> 5;
    const int lane = tid & 31;
    const int g    = lane >> 3;          // edge group 0..3
    const int q    = lane & 7;           // dim slice: halves [8q .. 8q+7]
    const int row  = blockIdx.x * ROWS_PER_BLOCK + wid;

    const int start = __ldg(&g_row_ptr[row]);
    const int end   = __ldg(&g_row_ptr[row + 1]);

    const uint4* __restrict__ emb16 = reinterpret_cast<const uint4*>(g_emb_h);

    unsigned long long A0 = 0ull, A1 = 0ull, A2 = 0ull, A3 = 0ull;

    int e = start;
    // Main: full 8-edge chunks, straight-line unpredicated loads.
    for (; e + 8 <= end; e += 8) {
        const int   c0 = __ldg(col_idx + e + g);
        const int   c1 = __ldg(col_idx + e + 4 + g);
        const float v0 = __ldg(vals + e + g);
        const float v1 = __ldg(vals + e + 4 + g);
        const uint4 x0 = __ldg(emb16 + (size_t)c0 * 8 + q);
        const uint4 x1 = __ldg(emb16 + (size_t)c1 * 8 + q);

        const unsigned long long vv0 = pk2(v0, v0);
        const unsigned long long vv1 = pk2(v1, v1);

        float2 f;
        f = __half22float2(*reinterpret_cast<const __half2*>(&x0.x));
        ffma2(A0, pk2(f.x, f.y), vv0);
        f = __half22float2(*reinterpret_cast<const __half2*>(&x0.y));
        ffma2(A1, pk2(f.x, f.y), vv0);
        f = __half22float2(*reinterpret_cast<const __half2*>(&x0.z));
        ffma2(A2, pk2(f.x, f.y), vv0);
        f = __half22float2(*reinterpret_cast<const __half2*>(&x0.w));
        ffma2(A3, pk2(f.x, f.y), vv0);

        f = __half22float2(*reinterpret_cast<const __half2*>(&x1.x));
        ffma2(A0, pk2(f.x, f.y), vv1);
        f = __half22float2(*reinterpret_cast<const __half2*>(&x1.y));
        ffma2(A1, pk2(f.x, f.y), vv1);
        f = __half22float2(*reinterpret_cast<const __half2*>(&x1.z));
        ffma2(A2, pk2(f.x, f.y), vv1);
        f = __half22float2(*reinterpret_cast<const __half2*>(&x1.w));
        ffma2(A3, pk2(f.x, f.y), vv1);
    }

    // Unpack packed accumulators.
    float2 u0 = unpk2(A0), u1 = unpk2(A1), u2 = unpk2(A2), u3 = unpk2(A3);
    float a0 = u0.x, a1 = u0.y, a2 = u1.x, a3 = u1.y;
    float a4 = u2.x, a5 = u2.y, a6 = u3.x, a7 = u3.y;

    // Tail: < 8 edges, clamped indices + selected values (rare path).
    if (e < end) {
        const int endm1 = end - 1;
        for (; e < end; e += 4) {
            const int eidx = e + g;
            const int idx  = min(eidx, endm1);
            const int   c  = __ldg(col_idx + idx);
            const float vl = __ldg(vals + idx);
            const float v  = (eidx < end) ? vl : 0.0f;
            const uint4 x  = __ldg(emb16 + (size_t)c * 8 + q);
            float2 f;
            f = __half22float2(*reinterpret_cast<const __half2*>(&x.x));
            a0 = fmaf(v, f.x, a0);  a1 = fmaf(v, f.y, a1);
            f = __half22float2(*reinterpret_cast<const __half2*>(&x.y));
            a2 = fmaf(v, f.x, a2);  a3 = fmaf(v, f.y, a3);
            f = __half22float2(*reinterpret_cast<const __half2*>(&x.z));
            a4 = fmaf(v, f.x, a4);  a5 = fmaf(v, f.y, a5);
            f = __half22float2(*reinterpret_cast<const __half2*>(&x.w));
            a6 = fmaf(v, f.x, a6);  a7 = fmaf(v, f.y, a7);
        }
    }

    // Fold the 4 edge groups: g2,g3 -> g0,g1 then g1 -> g0.
    #pragma unroll
    for (int ofs = 16; ofs >= 8; ofs >>= 1) {
        a0 += __shfl_down_sync(0xffffffffu, a0, ofs);
        a1 += __shfl_down_sync(0xffffffffu, a1, ofs);
        a2 += __shfl_down_sync(0xffffffffu, a2, ofs);
        a3 += __shfl_down_sync(0xffffffffu, a3, ofs);
        a4 += __shfl_down_sync(0xffffffffu, a4, ofs);
        a5 += __shfl_down_sync(0xffffffffu, a5, ofs);
        a6 += __shfl_down_sync(0xffffffffu, a6, ofs);
        a7 += __shfl_down_sync(0xffffffffu, a7, ofs);
    }

    // Lanes 0-7 store the 256B fp32 row (coalesced).
    if (g == 0) {
        float4* o4 = reinterpret_cast<float4*>(out + (size_t)row * D_FEAT + q * 8);
        o4[0] = make_float4(a0, a1, a2, a3);
        o4[1] = make_float4(a4, a5, a6, a7);
    }
}

extern "C" void kernel_launch(void* const* d_in, const int* in_sizes, int n_in,
                              void* d_out, int out_size) {
    const int*   row_idx = (const int*)  d_in[0];
    const int*   col_idx = (const int*)  d_in[1];
    const float* vals    = (const float*)d_in[2];
    const float* embeds  = (const float*)d_in[3];
    float*       out     = (float*)d_out;

    prep_kernel<<<(N_EDGES + 1 + 255) / 256, 256>>>(row_idx, embeds);

    const int blocks = N_NODES / ROWS_PER_BLOCK;   // 6250
    gcn_spmm_kernel<<<blocks, ROWS_PER_BLOCK * 32>>>(col_idx, vals, out);
}